// round 7
// baseline (speedup 1.0000x reference)
#include <cuda_runtime.h>
#include <cuda_fp16.h>

#define EPS_W  1e-8f
#define EPS_LN 1e-5f
// combined rows: etrc(64*4=256) + fc(256) + sc(512) + oftt(128*64=8192)
#define NROWS  9216
#define DOUT   256

// Fused, column-permuted fp16 table.
// Row r, physical half index 8*l+c (l in [0,32), c in [0,8)):
//   c<4  -> logical output col 4*l+c ; c>=4 -> col 128 + 4*l + (c-4)
// One uint4 load at 16B*l gives lane l exactly its 8 owned columns.
// Row blocks: [0,256)=etrc (bias folded), [256,512)=fc, [512,1024)=sc,
//             [1024,9216)=oftt (of*64+tt)
__device__ __align__(16) __half g_Ph[NROWS * DOUT];
__device__ float g_scale;
__device__ int   g_stride;   // 2 if indices are int64 (read low words), 1 if int32

// ---------------------------------------------------------------------------
// Detect index dtype (int64 vs int32) by inspecting odd 32-bit words.
__global__ void k_detect(const int* __restrict__ ev) {
    __shared__ int any;
    if (threadIdx.x == 0) any = 0;
    __syncthreads();
    int nz = 0;
    for (int i = threadIdx.x; i < 256; i += blockDim.x)
        if (ev[2 * i + 1] != 0) nz = 1;
    if (nz) atomicOr(&any, 1);
    __syncthreads();
    if (threadIdx.x == 0) g_stride = any ? 1 : 2;
}

// ---------------------------------------------------------------------------
// scale = mean(|W|) over 256*96 elements
__global__ void k_scale(const float* __restrict__ W) {
    __shared__ float red[32];
    int tid = threadIdx.x;  // 1024 threads
    float s = 0.f;
    for (int i = tid; i < 24576; i += 1024) s += fabsf(W[i]);
    #pragma unroll
    for (int o = 16; o > 0; o >>= 1) s += __shfl_xor_sync(~0u, s, o);
    if ((tid & 31) == 0) red[tid >> 5] = s;
    __syncthreads();
    if (tid < 32) {
        float v = red[tid];
        #pragma unroll
        for (int o = 16; o > 0; o >>= 1) v += __shfl_xor_sync(~0u, v, o);
        if (tid == 0) g_scale = v / 24576.0f;
    }
}

// ---------------------------------------------------------------------------
__device__ __forceinline__ float qdot16(const float* __restrict__ E, int v,
                                        const float* __restrict__ W, int o,
                                        int t, float scale, float inv, float acc) {
    #pragma unroll
    for (int k = 0; k < 16; k++) {
        float w = W[o * 96 + t * 16 + k];
        float q = rintf(w * inv);                 // round-half-to-even == jnp.round
        q = fminf(1.0f, fmaxf(-1.0f, q));
        acc = fmaf(E[v * 16 + k], q * scale, acc);
    }
    return acc;
}

// Build permuted fp16 table: one block per row, 256 threads = output channels.
__global__ void k_build(const float* __restrict__ W, const float* __restrict__ bias,
                        const float* __restrict__ E_et, const float* __restrict__ E_fc,
                        const float* __restrict__ E_sc, const float* __restrict__ E_of,
                        const float* __restrict__ E_tt, const float* __restrict__ E_rc) {
    int r = blockIdx.x, o = threadIdx.x;
    float scale = g_scale;
    float inv = 1.0f / (scale + EPS_W);
    float acc;
    if (r < 256) {           // etrc: r = et*4 + rc ; fold bias here
        acc = bias[o];
        acc = qdot16(E_et, r >> 2, W, o, 0, scale, inv, acc);
        acc = qdot16(E_rc, r & 3,  W, o, 5, scale, inv, acc);
    } else if (r < 512) {    // fc
        acc = qdot16(E_fc, r - 256, W, o, 1, scale, inv, 0.0f);
    } else if (r < 1024) {   // sc
        acc = qdot16(E_sc, r - 512, W, o, 2, scale, inv, 0.0f);
    } else {                 // oftt: rr = of*64 + tt
        int rr = r - 1024;
        acc = qdot16(E_of, rr >> 6, W, o, 3, scale, inv, 0.0f);
        acc = qdot16(E_tt, rr & 63, W, o, 4, scale, inv, acc);
    }
    // permuted position
    int c = (o < 128) ? (((o >> 2) << 3) + (o & 3))
                      : ((((o - 128) >> 2) << 3) + 4 + ((o - 128) & 3));
    g_Ph[r * DOUT + c] = __float2half(acc);
}

// ---------------------------------------------------------------------------
__device__ __forceinline__ __half2 h2(unsigned u) { return *reinterpret_cast<__half2*>(&u); }

// Main: one warp per token, 32-token tiles; lane owns cols [4l,4l+4) and
// [128+4l, +4). 4 uint4 gathers/token, fp16 accumulation, fp32 LN.
__global__ void __launch_bounds__(256) k_main(
    const int* __restrict__ i0, const int* __restrict__ i1,
    const int* __restrict__ i2, const int* __restrict__ i3,
    const int* __restrict__ i4, const int* __restrict__ i5,
    const float* __restrict__ gamma, const float* __restrict__ beta,
    float* __restrict__ out, int ntok)
{
    const uint4* __restrict__ Pu = (const uint4*)g_Ph;   // 32 uint4 per row
    int lane  = threadIdx.x & 31;
    int warp  = blockIdx.x * (blockDim.x >> 5) + (threadIdx.x >> 5);
    int nwarp = gridDim.x * (blockDim.x >> 5);
    int stride = g_stride;

    float4 gg0 = ((const float4*)gamma)[lane];
    float4 gg1 = ((const float4*)gamma)[lane + 32];
    float4 bb0 = ((const float4*)beta )[lane];
    float4 bb1 = ((const float4*)beta )[lane + 32];

    int ntiles = (ntok + 31) >> 5;
    for (int tile = warp; tile < ntiles; tile += nwarp) {
        int t0 = tile << 5;
        int nt = min(32, ntok - t0);

        // Coalesced per-lane index loads (lane j -> token t0+j),
        // premultiplied to uint4 row offsets (32 uint4 per row).
        int a0 = 0, a1 = 0, a2 = 0, a3 = 0;
        if (lane < nt) {
            size_t ti = (size_t)(t0 + lane) * (size_t)stride;
            a0 = (        (i0[ti] << 2) + i5[ti]) * 32;   // etrc = et*4 + rc
            a1 = ( 256 +  i1[ti])                 * 32;   // fc
            a2 = ( 512 +  i2[ti])                 * 32;   // sc
            a3 = (1024 + (i3[ti] << 6) + i4[ti])  * 32;   // oftt = of*64 + tt
        }

        for (int j = 0; j < nt; j++) {
            int b0 = __shfl_sync(~0u, a0, j) + lane;
            int b1 = __shfl_sync(~0u, a1, j) + lane;
            int b2 = __shfl_sync(~0u, a2, j) + lane;
            int b3 = __shfl_sync(~0u, a3, j) + lane;

            // 4 gathers (one uint4 each), issued up front for MLP.
            uint4 q0 = Pu[b0];
            uint4 q1 = Pu[b1];
            uint4 q2 = Pu[b2];
            uint4 q3 = Pu[b3];

            // fp16 accumulation: 4 half2 slots x 3 adds
            __half2 h0 = __hadd2(h2(q0.x), h2(q1.x));
            __half2 h1 = __hadd2(h2(q0.y), h2(q1.y));
            __half2 h2v= __hadd2(h2(q0.z), h2(q1.z));
            __half2 h3 = __hadd2(h2(q0.w), h2(q1.w));
            h0 = __hadd2(h0, h2(q2.x));  h1 = __hadd2(h1, h2(q2.y));
            h2v= __hadd2(h2v,h2(q2.z));  h3 = __hadd2(h3, h2(q2.w));
            h0 = __hadd2(h0, h2(q3.x));  h1 = __hadd2(h1, h2(q3.y));
            h2v= __hadd2(h2v,h2(q3.z));  h3 = __hadd2(h3, h2(q3.w));

            // convert once to fp32
            float2 f0 = __half22float2(h0);
            float2 f1 = __half22float2(h1);
            float2 f2 = __half22float2(h2v);
            float2 f3 = __half22float2(h3);
            float4 z0 = make_float4(f0.x, f0.y, f1.x, f1.y);   // cols 4l..4l+3
            float4 z1 = make_float4(f2.x, f2.y, f3.x, f3.y);   // cols 128+4l..

            float s  = z0.x + z0.y + z0.z + z0.w + z1.x + z1.y + z1.z + z1.w;
            float sq = z0.x*z0.x + z0.y*z0.y + z0.z*z0.z + z0.w*z0.w
                     + z1.x*z1.x + z1.y*z1.y + z1.z*z1.z + z1.w*z1.w;
            #pragma unroll
            for (int o = 16; o > 0; o >>= 1) {
                s  += __shfl_xor_sync(~0u, s,  o);
                sq += __shfl_xor_sync(~0u, sq, o);
            }

            float mu   = s * (1.0f / 256.0f);
            float var  = sq * (1.0f / 256.0f) - mu * mu;
            float rstd = rsqrtf(var + EPS_LN);

            float4* op = (float4*)(out + (size_t)(t0 + j) * DOUT);
            float4 o0, o1;
            o0.x = (z0.x - mu) * rstd * gg0.x + bb0.x;
            o0.y = (z0.y - mu) * rstd * gg0.y + bb0.y;
            o0.z = (z0.z - mu) * rstd * gg0.z + bb0.z;
            o0.w = (z0.w - mu) * rstd * gg0.w + bb0.w;
            o1.x = (z1.x - mu) * rstd * gg1.x + bb1.x;
            o1.y = (z1.y - mu) * rstd * gg1.y + bb1.y;
            o1.z = (z1.z - mu) * rstd * gg1.z + bb1.z;
            o1.w = (z1.w - mu) * rstd * gg1.w + bb1.w;
            __stcs(op + lane,      o0);   // streaming store: keep L2 for the table
            __stcs(op + 32 + lane, o1);
        }
    }
}

// ---------------------------------------------------------------------------
extern "C" void kernel_launch(void* const* d_in, const int* in_sizes, int n_in,
                              void* d_out, int out_size) {
    // Inputs (metadata order):
    // 0..5 : event_type, fault_class, syscall_class, opcode_family,
    //        transition_type, result_class        [B,S] integer
    // 6..11: E_et[64,16] E_fc[256,16] E_sc[512,16] E_of[128,16] E_tt[64,16] E_rc[4,16]
    // 12: W[256,96]  13: b[256]  14: gamma[256]  15: beta[256]
    int ntok = in_sizes[0];

    k_detect<<<1, 256>>>((const int*)d_in[0]);
    k_scale<<<1, 1024>>>((const float*)d_in[12]);
    k_build<<<NROWS, 256>>>((const float*)d_in[12], (const float*)d_in[13],
                            (const float*)d_in[6], (const float*)d_in[7],
                            (const float*)d_in[8], (const float*)d_in[9],
                            (const float*)d_in[10], (const float*)d_in[11]);
    k_main<<<2048, 256>>>((const int*)d_in[0], (const int*)d_in[1],
                          (const int*)d_in[2], (const int*)d_in[3],
                          (const int*)d_in[4], (const int*)d_in[5],
                          (const float*)d_in[14], (const float*)d_in[15],
                          (float*)d_out, ntok);
}

// round 8
// speedup vs baseline: 2.1375x; 2.1375x over previous
#include <cuda_runtime.h>
#include <cuda_fp16.h>

#define EPS_W  1e-8f
#define EPS_LN 1e-5f
// final rows: etrc(64*4=256) + fc(256) + sc(512) + oftt(128*64=8192)
#define NROWS  9216
#define DOUT   256

// Fused, column-permuted fp16 table.
// Row r, physical half index 8*l+c (l in [0,32), c in [0,8)):
//   c<4  -> logical output col 4*l+c ; c>=4 -> col 128 + 4*l + (c-4)
// One uint4 load at 16B*l gives lane l exactly its 8 owned columns.
// Row blocks: [0,256)=etrc (bias folded), [256,512)=fc, [512,1024)=sc,
//             [1024,9216)=oftt (of*64+tt)
__device__ __align__(16) __half g_Ph[NROWS * DOUT];
// quantized weights (w_eff = clip(rint(W/scale))*scale), computed ONCE
__device__ __align__(16) float g_Wq[256 * 96];
// fp32 permuted scratch rows: et[0,64) rc[64,68) of[68,196) tt[196,260)
__device__ __align__(16) float g_Pf[260 * DOUT];
__device__ int g_stride;   // 2 if indices are int64 (read low words), 1 if int32

// ---------------------------------------------------------------------------
// Detect index dtype (int64 vs int32) by inspecting odd 32-bit words.
__global__ void k_detect(const int* __restrict__ ev) {
    __shared__ int any;
    if (threadIdx.x == 0) any = 0;
    __syncthreads();
    int nz = 0;
    for (int i = threadIdx.x; i < 256; i += blockDim.x)
        if (ev[2 * i + 1] != 0) nz = 1;
    if (nz) atomicOr(&any, 1);
    __syncthreads();
    if (threadIdx.x == 0) g_stride = any ? 1 : 2;
}

// ---------------------------------------------------------------------------
// One block: scale = mean(|W|), then quantize all of W once into g_Wq.
__global__ void k_scale_quant(const float* __restrict__ W) {
    __shared__ float red[32];
    __shared__ float s_scale;
    int tid = threadIdx.x;  // 1024 threads
    float s = 0.f;
    for (int i = tid; i < 24576; i += 1024) s += fabsf(W[i]);
    #pragma unroll
    for (int o = 16; o > 0; o >>= 1) s += __shfl_xor_sync(~0u, s, o);
    if ((tid & 31) == 0) red[tid >> 5] = s;
    __syncthreads();
    if (tid < 32) {
        float v = red[tid];
        #pragma unroll
        for (int o = 16; o > 0; o >>= 1) v += __shfl_xor_sync(~0u, v, o);
        if (tid == 0) s_scale = v / 24576.0f;
    }
    __syncthreads();
    float scale = s_scale;
    float inv = 1.0f / (scale + EPS_W);
    for (int i = tid; i < 24576; i += 1024) {
        float q = rintf(W[i] * inv);              // round-half-to-even == jnp.round
        q = fminf(1.0f, fmaxf(-1.0f, q));
        g_Wq[i] = q * scale;
    }
}

// ---------------------------------------------------------------------------
__device__ __forceinline__ int permcol(int o) {
    return (o < 128) ? (((o >> 2) << 3) + (o & 3))
                     : ((((o - 128) >> 2) << 3) + 4 + ((o - 128) & 3));
}

__device__ __forceinline__ float qdotq(const float* __restrict__ E, int v,
                                       int o, int t, float acc) {
    #pragma unroll
    for (int k = 0; k < 16; k++)
        acc = fmaf(E[v * 16 + k], g_Wq[o * 96 + t * 16 + k], acc);
    return acc;
}

// Per-table projection rows (1028 blocks, 256 threads = output channels).
// fc/sc go straight to the final fp16 table; et/rc/of/tt to fp32 scratch.
__global__ void k_small(const float* __restrict__ bias,
                        const float* __restrict__ E_et, const float* __restrict__ E_fc,
                        const float* __restrict__ E_sc, const float* __restrict__ E_of,
                        const float* __restrict__ E_tt, const float* __restrict__ E_rc) {
    int r = blockIdx.x, o = threadIdx.x;
    int c = permcol(o);
    if (r < 64) {                       // et -> scratch
        g_Pf[r * DOUT + c] = qdotq(E_et, r, o, 0, 0.0f);
    } else if (r < 68) {                // rc -> scratch (bias folded)
        g_Pf[r * DOUT + c] = qdotq(E_rc, r - 64, o, 5, bias[o]);
    } else if (r < 324) {               // fc -> final
        g_Ph[(256 + r - 68) * DOUT + c] = __float2half(qdotq(E_fc, r - 68, o, 1, 0.0f));
    } else if (r < 836) {               // sc -> final
        g_Ph[(512 + r - 324) * DOUT + c] = __float2half(qdotq(E_sc, r - 324, o, 2, 0.0f));
    } else if (r < 964) {               // of -> scratch
        g_Pf[(68 + r - 836) * DOUT + c] = qdotq(E_of, r - 836, o, 3, 0.0f);
    } else {                            // tt -> scratch
        g_Pf[(196 + r - 964) * DOUT + c] = qdotq(E_tt, r - 964, o, 4, 0.0f);
    }
}

// ---------------------------------------------------------------------------
// Compose pair-sum rows: etrc(256) then oftt(8192) = 8448 rows; 4 rows/block.
__global__ void k_fuse() {
    int row = blockIdx.x * 4 + (threadIdx.x >> 6);   // 0..8447
    int t   = threadIdx.x & 63;                      // float4 index within row
    const float4* A; const float4* B; int dst;
    if (row < 256) {
        A = (const float4*)(g_Pf + (row >> 2) * DOUT);          // et
        B = (const float4*)(g_Pf + (64 + (row & 3)) * DOUT);    // rc (+bias)
        dst = row;
    } else {
        int rr = row - 256;
        A = (const float4*)(g_Pf + (68 + (rr >> 6)) * DOUT);    // of
        B = (const float4*)(g_Pf + (196 + (rr & 63)) * DOUT);   // tt
        dst = 1024 + rr;
    }
    float4 a = A[t], b = B[t];
    __half2 lo = __floats2half2_rn(a.x + b.x, a.y + b.y);
    __half2 hi = __floats2half2_rn(a.z + b.z, a.w + b.w);
    uint2 w = make_uint2(*(unsigned*)&lo, *(unsigned*)&hi);
    ((uint2*)(g_Ph + dst * DOUT))[t] = w;
}

// ---------------------------------------------------------------------------
__device__ __forceinline__ __half2 h2(unsigned u) { return *reinterpret_cast<__half2*>(&u); }

// Main: one warp per token, 32-token tiles; lane owns cols [4l,4l+4) and
// [128+4l, +4). 4 uint4 gathers/token, fp16 accumulation, fp32 LN.
__global__ void __launch_bounds__(256) k_main(
    const int* __restrict__ i0, const int* __restrict__ i1,
    const int* __restrict__ i2, const int* __restrict__ i3,
    const int* __restrict__ i4, const int* __restrict__ i5,
    const float* __restrict__ gamma, const float* __restrict__ beta,
    float* __restrict__ out, int ntok)
{
    const uint4* __restrict__ Pu = (const uint4*)g_Ph;   // 32 uint4 per row
    int lane  = threadIdx.x & 31;
    int warp  = blockIdx.x * (blockDim.x >> 5) + (threadIdx.x >> 5);
    int nwarp = gridDim.x * (blockDim.x >> 5);
    int stride = g_stride;

    float4 gg0 = ((const float4*)gamma)[lane];
    float4 gg1 = ((const float4*)gamma)[lane + 32];
    float4 bb0 = ((const float4*)beta )[lane];
    float4 bb1 = ((const float4*)beta )[lane + 32];

    int ntiles = (ntok + 31) >> 5;
    for (int tile = warp; tile < ntiles; tile += nwarp) {
        int t0 = tile << 5;
        int nt = min(32, ntok - t0);

        // Coalesced per-lane index loads (lane j -> token t0+j),
        // premultiplied to uint4 row offsets (32 uint4 per row).
        int a0 = 0, a1 = 0, a2 = 0, a3 = 0;
        if (lane < nt) {
            size_t ti = (size_t)(t0 + lane) * (size_t)stride;
            a0 = (        (i0[ti] << 2) + i5[ti]) * 32;   // etrc = et*4 + rc
            a1 = ( 256 +  i1[ti])                 * 32;   // fc
            a2 = ( 512 +  i2[ti])                 * 32;   // sc
            a3 = (1024 + (i3[ti] << 6) + i4[ti])  * 32;   // oftt = of*64 + tt
        }

        for (int j = 0; j < nt; j++) {
            int b0 = __shfl_sync(~0u, a0, j) + lane;
            int b1 = __shfl_sync(~0u, a1, j) + lane;
            int b2 = __shfl_sync(~0u, a2, j) + lane;
            int b3 = __shfl_sync(~0u, a3, j) + lane;

            // 4 gathers (one uint4 each), issued up front for MLP.
            uint4 q0 = Pu[b0];
            uint4 q1 = Pu[b1];
            uint4 q2 = Pu[b2];
            uint4 q3 = Pu[b3];

            // fp16 accumulation: 4 half2 slots x 3 adds
            __half2 h0 = __hadd2(h2(q0.x), h2(q1.x));
            __half2 h1 = __hadd2(h2(q0.y), h2(q1.y));
            __half2 h2v= __hadd2(h2(q0.z), h2(q1.z));
            __half2 h3 = __hadd2(h2(q0.w), h2(q1.w));
            h0 = __hadd2(h0, h2(q2.x));  h1 = __hadd2(h1, h2(q2.y));
            h2v= __hadd2(h2v,h2(q2.z));  h3 = __hadd2(h3, h2(q2.w));
            h0 = __hadd2(h0, h2(q3.x));  h1 = __hadd2(h1, h2(q3.y));
            h2v= __hadd2(h2v,h2(q3.z));  h3 = __hadd2(h3, h2(q3.w));

            // convert once to fp32
            float2 f0 = __half22float2(h0);
            float2 f1 = __half22float2(h1);
            float2 f2 = __half22float2(h2v);
            float2 f3 = __half22float2(h3);
            float4 z0 = make_float4(f0.x, f0.y, f1.x, f1.y);   // cols 4l..4l+3
            float4 z1 = make_float4(f2.x, f2.y, f3.x, f3.y);   // cols 128+4l..

            float s  = z0.x + z0.y + z0.z + z0.w + z1.x + z1.y + z1.z + z1.w;
            float sq = z0.x*z0.x + z0.y*z0.y + z0.z*z0.z + z0.w*z0.w
                     + z1.x*z1.x + z1.y*z1.y + z1.z*z1.z + z1.w*z1.w;
            #pragma unroll
            for (int o = 16; o > 0; o >>= 1) {
                s  += __shfl_xor_sync(~0u, s,  o);
                sq += __shfl_xor_sync(~0u, sq, o);
            }

            float mu   = s * (1.0f / 256.0f);
            float var  = sq * (1.0f / 256.0f) - mu * mu;
            float rstd = rsqrtf(var + EPS_LN);

            float4* op = (float4*)(out + (size_t)(t0 + j) * DOUT);
            float4 o0, o1;
            o0.x = (z0.x - mu) * rstd * gg0.x + bb0.x;
            o0.y = (z0.y - mu) * rstd * gg0.y + bb0.y;
            o0.z = (z0.z - mu) * rstd * gg0.z + bb0.z;
            o0.w = (z0.w - mu) * rstd * gg0.w + bb0.w;
            o1.x = (z1.x - mu) * rstd * gg1.x + bb1.x;
            o1.y = (z1.y - mu) * rstd * gg1.y + bb1.y;
            o1.z = (z1.z - mu) * rstd * gg1.z + bb1.z;
            o1.w = (z1.w - mu) * rstd * gg1.w + bb1.w;
            __stcs(op + lane,      o0);   // streaming store: keep L2 for the table
            __stcs(op + 32 + lane, o1);
        }
    }
}

// ---------------------------------------------------------------------------
extern "C" void kernel_launch(void* const* d_in, const int* in_sizes, int n_in,
                              void* d_out, int out_size) {
    // Inputs (metadata order):
    // 0..5 : event_type, fault_class, syscall_class, opcode_family,
    //        transition_type, result_class        [B,S] integer
    // 6..11: E_et[64,16] E_fc[256,16] E_sc[512,16] E_of[128,16] E_tt[64,16] E_rc[4,16]
    // 12: W[256,96]  13: b[256]  14: gamma[256]  15: beta[256]
    int ntok = in_sizes[0];

    k_detect<<<1, 256>>>((const int*)d_in[0]);
    k_scale_quant<<<1, 1024>>>((const float*)d_in[12]);
    k_small<<<1028, 256>>>((const float*)d_in[13],
                           (const float*)d_in[6], (const float*)d_in[7],
                           (const float*)d_in[8], (const float*)d_in[9],
                           (const float*)d_in[10], (const float*)d_in[11]);
    k_fuse<<<2112, 256>>>();
    k_main<<<2048, 256>>>((const int*)d_in[0], (const int*)d_in[1],
                          (const int*)d_in[2], (const int*)d_in[3],
                          (const int*)d_in[4], (const int*)d_in[5],
                          (const float*)d_in[14], (const float*)d_in[15],
                          (float*)d_out, ntok);
}